// round 9
// baseline (speedup 1.0000x reference)
#include <cuda_runtime.h>
#include <cstdint>

// FrozenBNBEmbedding: out[t, d] = code[ weight[input[t], d] ] * absmax[input[t]]
// DIM == BLOCK == 4096 -> absmax index == vocab row index.
//
// Inputs (metadata order):
//   d_in[0] = input  : int32 [4, 2048]       (8192 token ids)
//   d_in[1] = weight : int32 [50400, 4096]   (int8 codes as int32)
//   d_in[2] = absmax : float32 [50400]
//   d_in[3] = code   : float32 [256]
//   d_out   = float32 [4, 2048, 4096]
//
// Round-7: persistent-CTA cp.async.bulk ring pipeline.
//   - 296 CTAs (2/SM) x 1024 threads, each CTA strides tokens t = bid + i*296.
//   - 4-stage ring of 16KB row slots in smem, filled by cp.async.bulk
//     (global->shared, mbarrier complete_tx), issued by thread 0, 4 tokens
//     ahead: 64KB per CTA / 128KB per SM of reads permanently in flight,
//     independent of registers/warps. Token-id & absmax chase is pipelined.
//   - consumers: wait full-barrier (acquire), 1 int4/thread from the slot,
//     4 conflict-free lookups in a 32-way replicated LUT (32KB), 1 STG.128.
//   - __syncthreads() after consumption = backpressure for slot reuse.

#define DIM        4096
#define ROW_BYTES  (DIM * 4)      // 16384
#define NTOKENS    8192
#define THREADS    1024
#define NCTA       296            // 2 per SM on 148 SMs
#define STAGES     4
#define LUT_REP    32

// dynamic smem layout (bytes)
#define SMEM_LUT    0
#define LUT_BYTES   (256 * LUT_REP * 4)            // 32768
#define SMEM_RING   LUT_BYTES                       // 4 x 16384
#define SMEM_MBAR   (SMEM_RING + STAGES * ROW_BYTES)
#define SMEM_SCALE  (SMEM_MBAR + STAGES * 8)
#define SMEM_TOTAL  (SMEM_SCALE + STAGES * 4)       // 98352 -> ~98.4KB/CTA

__device__ __forceinline__ uint32_t smem_u32(const void* p) {
    return (uint32_t)__cvta_generic_to_shared(p);
}

__device__ __forceinline__ void mbar_init(uint32_t mbar, uint32_t cnt) {
    asm volatile("mbarrier.init.shared.b64 [%0], %1;" :: "r"(mbar), "r"(cnt) : "memory");
}

__device__ __forceinline__ void mbar_expect_tx(uint32_t mbar, uint32_t bytes) {
    asm volatile("mbarrier.arrive.expect_tx.shared.b64 _, [%0], %1;"
                 :: "r"(mbar), "r"(bytes) : "memory");
}

__device__ __forceinline__ void bulk_copy_g2s(uint32_t dst, const void* src,
                                              uint32_t bytes, uint32_t mbar) {
    asm volatile(
        "cp.async.bulk.shared::cluster.global.mbarrier::complete_tx::bytes "
        "[%0], [%1], %2, [%3];"
        :: "r"(dst), "l"(src), "r"(bytes), "r"(mbar) : "memory");
}

__device__ __forceinline__ void mbar_wait(uint32_t mbar, uint32_t parity) {
    uint32_t done;
    asm volatile(
        "{\n\t.reg .pred p;\n\t"
        "mbarrier.try_wait.parity.acquire.cta.shared::cta.b64 p, [%1], %2;\n\t"
        "selp.b32 %0, 1, 0, p;\n\t}"
        : "=r"(done) : "r"(mbar), "r"(parity) : "memory");
    if (!done) {
        asm volatile(
            "{\n\t.reg .pred P1;\n\t"
            "WAIT_LOOP_%=:\n\t"
            "mbarrier.try_wait.parity.acquire.cta.shared::cta.b64 P1, [%0], %1, 0x989680;\n\t"
            "@P1 bra.uni WAIT_DONE_%=;\n\t"
            "bra.uni WAIT_LOOP_%=;\n\t"
            "WAIT_DONE_%=:\n\t}"
            :: "r"(mbar), "r"(parity) : "memory");
    }
}

__global__ __launch_bounds__(THREADS, 2)
void bnb_embed_kernel(const int* __restrict__ input,
                      const int* __restrict__ weight,
                      const float* __restrict__ absmax,
                      const float* __restrict__ code,
                      float* __restrict__ out)
{
    extern __shared__ char smem[];
    float* s_lut   = reinterpret_cast<float*>(smem + SMEM_LUT);
    float* s_scale = reinterpret_cast<float*>(smem + SMEM_SCALE);

    const uint32_t ring_base = smem_u32(smem + SMEM_RING);
    const uint32_t mbar_base = smem_u32(smem + SMEM_MBAR);

    const int tid  = threadIdx.x;
    const int lane = tid & 31;
    const int bid  = blockIdx.x;

    // 32-way replicated LUT: word = code[w >> 5]; lookup s_lut[(byte<<5)+lane]
    // -> bank == lane, conflict-free. 8 STS/thread, once per persistent CTA.
    #pragma unroll
    for (int w = tid; w < 256 * LUT_REP; w += THREADS)
        s_lut[w] = __ldg(&code[w >> 5]);

    if (tid == 0) {
        #pragma unroll
        for (int s = 0; s < STAGES; s++)
            mbar_init(mbar_base + s * 8, 1);   // only the expect_tx arrive
    }
    __syncthreads();

    const float* __restrict__ lut = s_lut + lane;

    // Tokens this CTA owns: t = bid + i*NCTA, i in [0, count)
    const int count = (NTOKENS - bid + NCTA - 1) / NCTA;   // 27 or 28

    // Producer: fetch token id + scale, publish scale, expect_tx, issue bulk.
    auto produce = [&](int i) {
        const int t   = bid + i * NCTA;
        const int tok = __ldg(&input[t]);
        const float scale = __ldg(&absmax[tok]);
        const int slot = i & (STAGES - 1);
        s_scale[slot] = scale;                          // STS before arrive
        mbar_expect_tx(mbar_base + slot * 8, ROW_BYTES);
        bulk_copy_g2s(ring_base + slot * ROW_BYTES,
                      weight + (size_t)tok * DIM,
                      ROW_BYTES,
                      mbar_base + slot * 8);
    };

    // Prologue: fill the ring (count >= 27 > STAGES always).
    if (tid == 0) {
        #pragma unroll
        for (int k = 0; k < STAGES; k++)
            produce(k);
    }

    float4* __restrict__ out4 = reinterpret_cast<float4*>(out);

    #pragma unroll 1
    for (int i = 0; i < count; i++) {
        const int slot = i & (STAGES - 1);
        const uint32_t parity = (i >> 2) & 1;

        mbar_wait(mbar_base + slot * 8, parity);        // acquire

        const float scale = s_scale[slot];
        const int4* __restrict__ row =
            reinterpret_cast<const int4*>(smem + SMEM_RING + slot * ROW_BYTES);

        int4 q = row[tid];                               // LDS.128, coalesced
        float4 o;
        o.x = lut[(q.x & 255) << 5] * scale;
        o.y = lut[(q.y & 255) << 5] * scale;
        o.z = lut[(q.z & 255) << 5] * scale;
        o.w = lut[(q.w & 255) << 5] * scale;

        const size_t t = (size_t)bid + (size_t)i * NCTA;
        out4[t * (DIM / 4) + tid] = o;

        __syncthreads();                                 // slot fully consumed

        if (tid == 0 && i + STAGES < count)
            produce(i + STAGES);                         // refill freed slot
    }
}

extern "C" void kernel_launch(void* const* d_in, const int* in_sizes, int n_in,
                              void* d_out, int out_size)
{
    const int*   input  = (const int*)  d_in[0];
    const int*   weight = (const int*)  d_in[1];
    const float* absmax = (const float*)d_in[2];
    const float* code   = (const float*)d_in[3];
    float*       out    = (float*)d_out;

    cudaFuncSetAttribute(bnb_embed_kernel,
                         cudaFuncAttributeMaxDynamicSharedMemorySize,
                         SMEM_TOTAL);

    bnb_embed_kernel<<<NCTA, THREADS, SMEM_TOTAL>>>(input, weight, absmax, code, out);
}

// round 13
// speedup vs baseline: 1.0894x; 1.0894x over previous
#include <cuda_runtime.h>
#include <cstdint>

// FrozenBNBEmbedding: out[t, d] = code[ weight[input[t], d] ] * absmax[input[t]]
// DIM == BLOCK == 4096 -> absmax index == vocab row index.
//
// Inputs (metadata order):
//   d_in[0] = input  : int32 [4, 2048]       (8192 token ids)
//   d_in[1] = weight : int32 [50400, 4096]   (int8 codes as int32)
//   d_in[2] = absmax : float32 [50400]
//   d_in[3] = code   : float32 [256]
//   d_out   = float32 [4, 2048, 4096]
//
// Round-11: R1 skeleton + L2 policy hints via 256-bit accesses
// (sm_103a ptxas requires .v8.b32 for L2::evict_* modifiers).
//   - weight reads:  ld.global.nc.L2::evict_last.v8.b32  (keep gather set in L2)
//   - output writes: st.global.L2::evict_first.v8.b32    (dead stream, don't thrash)
//   - 32B/thread per access: 2 loads + 2 stores per thread total.

#define DIM      4096
#define NTOKENS  8192
#define THREADS  256

struct v8 { int x0, x1, x2, x3, x4, x5, x6, x7; };

__device__ __forceinline__ v8 ldg256_evict_last(const void* p) {
    v8 v;
    asm volatile(
        "ld.global.nc.L2::evict_last.v8.b32 {%0,%1,%2,%3,%4,%5,%6,%7}, [%8];"
        : "=r"(v.x0), "=r"(v.x1), "=r"(v.x2), "=r"(v.x3),
          "=r"(v.x4), "=r"(v.x5), "=r"(v.x6), "=r"(v.x7)
        : "l"(p));
    return v;
}

__device__ __forceinline__ void stg256_evict_first(void* p, float f0, float f1,
                                                   float f2, float f3, float f4,
                                                   float f5, float f6, float f7) {
    asm volatile(
        "st.global.L2::evict_first.v8.b32 [%0], {%1,%2,%3,%4,%5,%6,%7,%8};"
        :: "l"(p),
           "f"(f0), "f"(f1), "f"(f2), "f"(f3),
           "f"(f4), "f"(f5), "f"(f6), "f"(f7)
        : "memory");
}

__global__ __launch_bounds__(THREADS)
void bnb_embed_kernel(const int* __restrict__ input,
                      const int* __restrict__ weight,
                      const float* __restrict__ absmax,
                      const float* __restrict__ code,
                      float* __restrict__ out)
{
    __shared__ float s_code[256];
    s_code[threadIdx.x] = code[threadIdx.x];   // THREADS == 256
    __syncthreads();

    const int t   = blockIdx.x;                // token index 0..8191
    const int tok = input[t];                  // vocab row
    const float scale = __ldg(&absmax[tok]);

    const int*  wrow = weight + (size_t)tok * DIM;
    float*      orow = out    + (size_t)t   * DIM;

    const int i = threadIdx.x;

    // Two 32B loads per thread (64B), coalesced, MLP=2x256b in flight.
    v8 a = ldg256_evict_last(wrow + i * 8);
    v8 b = ldg256_evict_last(wrow + 2048 + i * 8);

    stg256_evict_first(orow + i * 8,
        s_code[a.x0 & 255] * scale, s_code[a.x1 & 255] * scale,
        s_code[a.x2 & 255] * scale, s_code[a.x3 & 255] * scale,
        s_code[a.x4 & 255] * scale, s_code[a.x5 & 255] * scale,
        s_code[a.x6 & 255] * scale, s_code[a.x7 & 255] * scale);

    stg256_evict_first(orow + 2048 + i * 8,
        s_code[b.x0 & 255] * scale, s_code[b.x1 & 255] * scale,
        s_code[b.x2 & 255] * scale, s_code[b.x3 & 255] * scale,
        s_code[b.x4 & 255] * scale, s_code[b.x5 & 255] * scale,
        s_code[b.x6 & 255] * scale, s_code[b.x7 & 255] * scale);
}

extern "C" void kernel_launch(void* const* d_in, const int* in_sizes, int n_in,
                              void* d_out, int out_size)
{
    const int*   input  = (const int*)  d_in[0];
    const int*   weight = (const int*)  d_in[1];
    const float* absmax = (const float*)d_in[2];
    const float* code   = (const float*)d_in[3];
    float*       out    = (float*)d_out;

    bnb_embed_kernel<<<NTOKENS, THREADS>>>(input, weight, absmax, code, out);
}

// round 15
// speedup vs baseline: 1.0956x; 1.0056x over previous
#include <cuda_runtime.h>
#include <cstdint>

// FrozenBNBEmbedding: out[t, d] = code[ weight[input[t], d] ] * absmax[input[t]]
// DIM == BLOCK == 4096 -> absmax index == vocab row index.
//
// Inputs (metadata order):
//   d_in[0] = input  : int32 [4, 2048]       (8192 token ids)
//   d_in[1] = weight : int32 [50400, 4096]   (int8 codes as int32)
//   d_in[2] = absmax : float32 [50400]
//   d_in[3] = code   : float32 [256]
//   d_out   = float32 [4, 2048, 4096]
//
// Round-14: R1 skeleton (best: 38.1us) + ONE change: streaming stores
// (st.global.cs). Goal: stop the write-once 134MB output stream from
// allocating/displacing the ~124MB gathered weight rows in L2 (126MB),
// so reads hit L2 across graph replays (currently 57% hit).

#define DIM      4096
#define NTOKENS  8192
#define THREADS  256

__device__ __forceinline__ void stg_cs(float4* p, float4 v) {
    asm volatile("st.global.cs.v4.f32 [%0], {%1,%2,%3,%4};"
                 :: "l"(p), "f"(v.x), "f"(v.y), "f"(v.z), "f"(v.w)
                 : "memory");
}

__global__ __launch_bounds__(THREADS)
void bnb_embed_kernel(const int* __restrict__ input,
                      const int* __restrict__ weight,
                      const float* __restrict__ absmax,
                      const float* __restrict__ code,
                      float* __restrict__ out)
{
    __shared__ float s_code[256];
    s_code[threadIdx.x] = code[threadIdx.x];   // THREADS == 256
    __syncthreads();

    const int t   = blockIdx.x;                // token index 0..8191
    const int tok = input[t];                  // vocab row
    const float scale = __ldg(&absmax[tok]);

    const int4* __restrict__ wrow =
        reinterpret_cast<const int4*>(weight + (size_t)tok * DIM);
    float4* __restrict__ orow =
        reinterpret_cast<float4*>(out + (size_t)t * DIM);

    const int i = threadIdx.x;

    // Front-batch all four 16B loads (MLP=4 per thread).
    int4 q0 = wrow[i];
    int4 q1 = wrow[i + 256];
    int4 q2 = wrow[i + 512];
    int4 q3 = wrow[i + 768];

    float4 o;
    o.x = s_code[q0.x & 255] * scale;
    o.y = s_code[q0.y & 255] * scale;
    o.z = s_code[q0.z & 255] * scale;
    o.w = s_code[q0.w & 255] * scale;
    stg_cs(&orow[i], o);

    o.x = s_code[q1.x & 255] * scale;
    o.y = s_code[q1.y & 255] * scale;
    o.z = s_code[q1.z & 255] * scale;
    o.w = s_code[q1.w & 255] * scale;
    stg_cs(&orow[i + 256], o);

    o.x = s_code[q2.x & 255] * scale;
    o.y = s_code[q2.y & 255] * scale;
    o.z = s_code[q2.z & 255] * scale;
    o.w = s_code[q2.w & 255] * scale;
    stg_cs(&orow[i + 512], o);

    o.x = s_code[q3.x & 255] * scale;
    o.y = s_code[q3.y & 255] * scale;
    o.z = s_code[q3.z & 255] * scale;
    o.w = s_code[q3.w & 255] * scale;
    stg_cs(&orow[i + 768], o);
}

extern "C" void kernel_launch(void* const* d_in, const int* in_sizes, int n_in,
                              void* d_out, int out_size)
{
    const int*   input  = (const int*)  d_in[0];
    const int*   weight = (const int*)  d_in[1];
    const float* absmax = (const float*)d_in[2];
    const float* code   = (const float*)d_in[3];
    float*       out    = (float*)d_out;

    bnb_embed_kernel<<<NTOKENS, THREADS>>>(input, weight, absmax, code, out);
}